// round 8
// baseline (speedup 1.0000x reference)
#include <cuda_runtime.h>
#include <cuda_bf16.h>

#define S_LEN 2048
#define B_SZ  16
#define H_DIM 1024

// 8 chunk-partial slabs: g_part[ch][b][h]  (race-free -> no init kernel)
__device__ float g_part[8][B_SZ * H_DIM];

// ---------------------------------------------------------------------------
// Kernel 1 v8: energy partials.
// j split into 8 chunks of 128 floats (32 float4). Block = 128 thr (4 warps)
// covers (8 h-rows) x (one chunk); warp owns 2 rows x 16 b = 32 accumulators,
// each LDS.128 feeds 8 FFMAs. grid = 128 rowgroups * 8 chunks = 1024 blocks
// (~28 warps/SM) -> latency hidden by occupancy + 32 independent chains.
// ---------------------------------------------------------------------------
__global__ void __launch_bounds__(128)
energy_kernel(const float* __restrict__ lds,
              const float* __restrict__ W)
{
    __shared__ float4 s_st[16 * 32];     // [b][32 float4] for this chunk (8KB)

    const int t    = threadIdx.x;
    const int warp = t >> 5;
    const int lane = t & 31;
    const int rg   = blockIdx.x >> 3;    // 8-row group (0..127)
    const int ch   = blockIdx.x & 7;     // j-chunk (128 floats = 32 float4)
    const int row0 = rg * 8 + warp * 2;  // first of this warp's 2 rows

    const float4* st4 = reinterpret_cast<const float4*>(lds);  // [B][256]
    const float4* W4  = reinterpret_cast<const float4*>(W);    // [H][256]

    // Stage state chunk: 512 float4, 128 threads -> 4 each.
    #pragma unroll
    for (int i = 0; i < 4; ++i) {
        const int v = t + i * 128;       // 0..511
        const int b = v >> 5;
        const int k = v & 31;
        s_st[v] = st4[b * 256 + ch * 32 + k];
    }
    __syncthreads();

    const float4 w0 = W4[(size_t)row0 * 256 + ch * 32 + lane];
    const float4 w1 = W4[(size_t)(row0 + 1) * 256 + ch * 32 + lane];

    float a[32];                          // a[r*16+b]
    #pragma unroll
    for (int b = 0; b < 16; ++b) {
        const float4 s = s_st[b * 32 + lane];
        a[b]      = w0.x * s.x + w0.y * s.y + w0.z * s.z + w0.w * s.w;
        a[16 + b] = w1.x * s.x + w1.y * s.y + w1.z * s.z + w1.w * s.w;
    }

    // Value-halving butterfly over 32 accumulators:
    // after all steps, lane l holds the warp-total of original a[l].
    int n = 32;
    #pragma unroll
    for (int s = 16; s >= 1; s >>= 1) {
        const int  half = n >> 1;
        const bool up   = (lane & s) != 0;
        #pragma unroll
        for (int i = 0; i < half; ++i) {
            const float send = up ? a[i] : a[i + half];
            const float keep = up ? a[i + half] : a[i];
            a[i] = keep + __shfl_xor_sync(0xFFFFFFFF, send, s);
        }
        n = half;
    }

    // lane l -> (r = l>>4, b = l&15)
    const int r = lane >> 4;
    const int b = lane & 15;
    g_part[ch][(size_t)b * H_DIM + row0 + r] = a[0];
}

// ---------------------------------------------------------------------------
// Kernel 2: scores[s][b] = sum_h enc[s][b][h] * energy[b][h]
// energy row reconstructed as sum of 8 partial slabs + bias (L2-resident).
// One block per (b, 8-row s-chunk): energy row in registers, reused 8x.
// ---------------------------------------------------------------------------
#define VPS 8
__global__ void __launch_bounds__(128, 8)
score_kernel(const float* __restrict__ enc,
             const float* __restrict__ bias,
             float* __restrict__ out)
{
    const int b  = blockIdx.x & (B_SZ - 1);
    const int s0 = (blockIdx.x >> 4) * VPS;
    const int t  = threadIdx.x;

    const float4* e4 = reinterpret_cast<const float4*>(enc);
    const float4* b4 = reinterpret_cast<const float4*>(bias);

    float4 g0 = b4[t];
    float4 g1 = b4[128 + t];
    #pragma unroll
    for (int c = 0; c < 8; ++c) {
        const float4* p4 = reinterpret_cast<const float4*>(g_part[c]);
        const float4 p0 = p4[b * (H_DIM / 4) + t];
        const float4 p1 = p4[b * (H_DIM / 4) + 128 + t];
        g0.x += p0.x; g0.y += p0.y; g0.z += p0.z; g0.w += p0.w;
        g1.x += p1.x; g1.y += p1.y; g1.z += p1.z; g1.w += p1.w;
    }

    float acc[VPS];
    #pragma unroll
    for (int i = 0; i < VPS; ++i) {
        const size_t row = ((size_t)(s0 + i) * B_SZ + b) * (H_DIM / 4);
        const float4 a0 = e4[row + t];
        const float4 a1 = e4[row + 128 + t];
        acc[i] = a0.x * g0.x + a0.y * g0.y + a0.z * g0.z + a0.w * g0.w
               + a1.x * g1.x + a1.y * g1.y + a1.z * g1.z + a1.w * g1.w;
    }

    #pragma unroll
    for (int i = 0; i < VPS; ++i)
        #pragma unroll
        for (int off = 16; off > 0; off >>= 1)
            acc[i] += __shfl_xor_sync(0xFFFFFFFF, acc[i], off);

    __shared__ float red[4][VPS];
    const int warp = t >> 5;
    const int lane = t & 31;
    if (lane == 0) {
        #pragma unroll
        for (int i = 0; i < VPS; ++i)
            red[warp][i] = acc[i];
    }
    __syncthreads();
    if (t < VPS)
        out[(size_t)(s0 + t) * B_SZ + b] =
            red[0][t] + red[1][t] + red[2][t] + red[3][t];
}

// ---------------------------------------------------------------------------
// Kernel 3: softmax over S per column b. 16 blocks x 1024 threads,
// 2 values/thread in registers, two block-wide reductions.
// ---------------------------------------------------------------------------
__global__ void __launch_bounds__(1024)
softmax_kernel(float* __restrict__ out)
{
    const int b = blockIdx.x;
    const int t = threadIdx.x;

    float v0 = out[(size_t)t * B_SZ + b];
    float v1 = out[(size_t)(t + 1024) * B_SZ + b];

    __shared__ float sm[32];
    const int warp = t >> 5, lane = t & 31;

    float mx = fmaxf(v0, v1);
    #pragma unroll
    for (int off = 16; off > 0; off >>= 1)
        mx = fmaxf(mx, __shfl_xor_sync(0xFFFFFFFF, mx, off));
    if (lane == 0) sm[warp] = mx;
    __syncthreads();
    if (warp == 0) {
        float m = sm[lane];
        #pragma unroll
        for (int off = 16; off > 0; off >>= 1)
            m = fmaxf(m, __shfl_xor_sync(0xFFFFFFFF, m, off));
        if (lane == 0) sm[0] = m;
    }
    __syncthreads();
    mx = sm[0];
    __syncthreads();

    v0 = __expf(v0 - mx);
    v1 = __expf(v1 - mx);
    float sum = v0 + v1;
    #pragma unroll
    for (int off = 16; off > 0; off >>= 1)
        sum += __shfl_xor_sync(0xFFFFFFFF, sum, off);
    if (lane == 0) sm[warp] = sum;
    __syncthreads();
    if (warp == 0) {
        float s = sm[lane];
        #pragma unroll
        for (int off = 16; off > 0; off >>= 1)
            s += __shfl_xor_sync(0xFFFFFFFF, s, off);
        if (lane == 0) sm[0] = s;
    }
    __syncthreads();
    const float inv = 1.0f / sm[0];

    out[(size_t)t * B_SZ + b]          = v0 * inv;
    out[(size_t)(t + 1024) * B_SZ + b] = v1 * inv;
}

// ---------------------------------------------------------------------------
extern "C" void kernel_launch(void* const* d_in, const int* in_sizes, int n_in,
                              void* d_out, int out_size)
{
    const float* enc  = (const float*)d_in[0];  // [S,B,H]
    const float* lds  = (const float*)d_in[1];  // [2,1,B,H]
    const float* W    = (const float*)d_in[2];  // [H,H]
    const float* bias = (const float*)d_in[3];  // [H]
    float* out = (float*)d_out;                 // [1,1,S,B] == [S,B]

    energy_kernel<<<1024, 128>>>(lds, W);
    score_kernel<<<(S_LEN / VPS) * B_SZ, 128>>>(enc, bias, out);
    softmax_kernel<<<B_SZ, 1024>>>(out);
}